// round 2
// baseline (speedup 1.0000x reference)
#include <cuda_runtime.h>
#include <cuda_fp16.h>
#include <math.h>

#define N_NODES 50000
#define N_EDGES 800000
#define E_TOT   (N_EDGES + N_NODES)
#define IN_DIM  128
#define HID     64
#define HEADS   4
#define OUT_DIM 20
#define NUM_GRAPHS 64
#define NEG_SLOPE 0.2f

// ---------------- scratch (static device globals; no allocation) -------------
__device__ float  g_h1  [N_NODES * HEADS * HID];   // x @ W1^T (fp32, for alpha)
__device__ __half g_h1h [N_NODES * HEADS * HID];   // fp16 copy for gather
__device__ float  g_h1o [N_NODES * HEADS * HID];   // elu(conv1 out)
__device__ float  g_h2  [N_NODES * HID];           // h1o @ W2^T (fp32, for alpha)
__device__ __half g_h2h [N_NODES * HID];           // fp16 copy for gather
__device__ float  g_as1 [N_NODES * HEADS];
__device__ float  g_ad1 [N_NODES * HEADS];
__device__ float  g_as2 [N_NODES];
__device__ float  g_ad2 [N_NODES];
__device__ int    g_deg   [N_NODES];
__device__ int    g_rowptr[N_NODES + 1];
__device__ int    g_woff  [N_NODES];
__device__ int    g_colsrc[E_TOT];
__device__ float  g_pooled[NUM_GRAPHS * HID];

// ---------------- f32x2 packed-FMA helpers (sm_103a) -------------------------
__device__ __forceinline__ void fma2(unsigned long long& d,
                                     unsigned long long a, unsigned long long b) {
    asm("fma.rn.f32x2 %0, %1, %2, %0;" : "+l"(d) : "l"(a), "l"(b));
}
__device__ __forceinline__ unsigned long long pack2(float x, float y) {
    unsigned long long r;
    asm("mov.b64 %0, {%1, %2};" : "=l"(r) : "f"(x), "f"(y));
    return r;
}
__device__ __forceinline__ void unpack2(unsigned long long v, float& x, float& y) {
    asm("mov.b64 {%0, %1}, %2;" : "=f"(x), "=f"(y) : "l"(v));
}

// ---------------- init ------------------------------------------------------
__global__ void k_init() {
    int i = blockIdx.x * blockDim.x + threadIdx.x;
    if (i < N_NODES) g_deg[i] = 0;
    if (i < NUM_GRAPHS * HID) ((int*)g_pooled)[i] = 0xFF800000; // -inf
}

// ---------------- SGEMM (NT) with packed f32x2 -------------------------------
// C[M,N] = A[M,K] * B[N,K]^T.  BM=128, BK=16, microtile 8x8.
// threads = 16*(BN/8). Also emits a __half copy of C.
template <int BN>
__global__ void k_gemm(const float* __restrict__ A, const float* __restrict__ B,
                       float* __restrict__ C, __half* __restrict__ Ch,
                       int M, int N, int K) {
    constexpr int BM = 128, BK = 16;
    constexpr int NT = 16 * (BN / 8);
    __shared__ float As[BK][BM];
    __shared__ float Bs[BK][BN];
    int tid = threadIdx.x;
    int tx = tid % (BN / 8), ty = tid / (BN / 8);
    int row0 = blockIdx.y * BM, col0 = blockIdx.x * BN;

    unsigned long long acc[8][4];
#pragma unroll
    for (int i = 0; i < 8; i++)
#pragma unroll
        for (int j = 0; j < 4; j++) acc[i][j] = 0ULL;

    for (int k0 = 0; k0 < K; k0 += BK) {
#pragma unroll
        for (int i = 0; i < (BM * 4) / NT; i++) {
            int idx = tid + i * NT;        // 0 .. BM*4-1
            int r = idx >> 2, kc = (idx & 3) * 4;
            int ar = row0 + r;
            float4 v = (ar < M) ? *(const float4*)(A + (size_t)ar * K + k0 + kc)
                                : make_float4(0.f, 0.f, 0.f, 0.f);
            As[kc + 0][r] = v.x; As[kc + 1][r] = v.y;
            As[kc + 2][r] = v.z; As[kc + 3][r] = v.w;
        }
#pragma unroll
        for (int i = 0; i < (BN * 4) / NT; i++) {
            int idx = tid + i * NT;        // 0 .. BN*4-1
            int r = idx >> 2, kc = (idx & 3) * 4;
            float4 v = *(const float4*)(B + (size_t)(col0 + r) * K + k0 + kc);
            Bs[kc + 0][r] = v.x; Bs[kc + 1][r] = v.y;
            Bs[kc + 2][r] = v.z; Bs[kc + 3][r] = v.w;
        }
        __syncthreads();
#pragma unroll
        for (int kk = 0; kk < BK; kk++) {
            float4 a0 = *(const float4*)&As[kk][ty * 8];
            float4 a1 = *(const float4*)&As[kk][ty * 8 + 4];
            float4 b0 = *(const float4*)&Bs[kk][tx * 8];
            float4 b1 = *(const float4*)&Bs[kk][tx * 8 + 4];
            unsigned long long bp[4] = {pack2(b0.x, b0.y), pack2(b0.z, b0.w),
                                        pack2(b1.x, b1.y), pack2(b1.z, b1.w)};
            float ar8[8] = {a0.x, a0.y, a0.z, a0.w, a1.x, a1.y, a1.z, a1.w};
#pragma unroll
            for (int i = 0; i < 8; i++) {
                unsigned long long ap = pack2(ar8[i], ar8[i]);
                fma2(acc[i][0], ap, bp[0]);
                fma2(acc[i][1], ap, bp[1]);
                fma2(acc[i][2], ap, bp[2]);
                fma2(acc[i][3], ap, bp[3]);
            }
        }
        __syncthreads();
    }
#pragma unroll
    for (int i = 0; i < 8; i++) {
        int r = row0 + ty * 8 + i;
        if (r >= M) continue;
        float o[8];
#pragma unroll
        for (int j = 0; j < 4; j++) unpack2(acc[i][j], o[2 * j], o[2 * j + 1]);
        float4* cp = (float4*)(C + (size_t)r * N + col0 + tx * 8);
        cp[0] = make_float4(o[0], o[1], o[2], o[3]);
        cp[1] = make_float4(o[4], o[5], o[6], o[7]);
        __align__(16) __half2 hh[4];
#pragma unroll
        for (int j = 0; j < 4; j++) hh[j] = __floats2half2_rn(o[2 * j], o[2 * j + 1]);
        *(float4*)(Ch + (size_t)r * N + col0 + tx * 8) = *(float4*)hh;
    }
}

// ---------------- alpha_src / alpha_dst dots (one warp per node-head) --------
template <int H>
__global__ void k_alpha(const float* __restrict__ hlin,
                        const float* __restrict__ a_s, const float* __restrict__ a_d,
                        float* __restrict__ as_o, float* __restrict__ ad_o) {
    int gw = (blockIdx.x * blockDim.x + threadIdx.x) >> 5;
    int lane = threadIdx.x & 31;
    if (gw >= N_NODES * H) return;
    int n = gw / H, h = gw % H;
    float2 hv = ((const float2*)(hlin + (size_t)n * H * HID + h * HID))[lane];
    float2 sv = ((const float2*)(a_s + h * HID))[lane];
    float2 dv = ((const float2*)(a_d + h * HID))[lane];
    float s = hv.x * sv.x + hv.y * sv.y;
    float d = hv.x * dv.x + hv.y * dv.y;
#pragma unroll
    for (int o = 16; o > 0; o >>= 1) {
        s += __shfl_xor_sync(0xffffffffu, s, o);
        d += __shfl_xor_sync(0xffffffffu, d, o);
    }
    if (lane == 0) { as_o[gw] = s; ad_o[gw] = d; }
}

// ---------------- CSR build --------------------------------------------------
__global__ void k_deg(const int* __restrict__ ei) {
    int i = blockIdx.x * blockDim.x + threadIdx.x;
    if (i >= E_TOT) return;
    int dst = (i < N_EDGES) ? ei[N_EDGES + i] : (i - N_EDGES);
    atomicAdd(&g_deg[dst], 1);
}

__global__ void k_scan() {   // single block, 1024 threads, 4 elems/thread/iter
    __shared__ int s_w[32];
    int tid = threadIdx.x, lane = tid & 31, w = tid >> 5;
    int carry = 0;
    for (int base = 0; base < N_NODES; base += 4096) {
        int i = base + tid * 4;
        int a0 = 0, a1 = 0, a2 = 0, a3 = 0;
        if (i + 3 < N_NODES) {
            int4 v = *(const int4*)&g_deg[i];
            a0 = v.x; a1 = v.y; a2 = v.z; a3 = v.w;
        } else {
            if (i     < N_NODES) a0 = g_deg[i];
            if (i + 1 < N_NODES) a1 = g_deg[i + 1];
            if (i + 2 < N_NODES) a2 = g_deg[i + 2];
            if (i + 3 < N_NODES) a3 = g_deg[i + 3];
        }
        int t = a0 + a1 + a2 + a3;
        int x = t;
#pragma unroll
        for (int o = 1; o < 32; o <<= 1) {
            int u = __shfl_up_sync(0xffffffffu, x, o);
            if (lane >= o) x += u;
        }
        if (lane == 31) s_w[w] = x;
        __syncthreads();
        if (w == 0) {
            int y = s_w[lane];
#pragma unroll
            for (int o = 1; o < 32; o <<= 1) {
                int u = __shfl_up_sync(0xffffffffu, y, o);
                if (lane >= o) y += u;
            }
            s_w[lane] = y;
        }
        __syncthreads();
        int excl = carry + (w ? s_w[w - 1] : 0) + (x - t);
        int r0 = excl, r1 = excl + a0, r2 = r1 + a1, r3 = r2 + a2;
        if (i + 3 < N_NODES) {
            *(int4*)&g_rowptr[i] = make_int4(r0, r1, r2, r3);
            *(int4*)&g_woff[i]   = make_int4(r0, r1, r2, r3);
        } else {
            if (i     < N_NODES) { g_rowptr[i]     = r0; g_woff[i]     = r0; }
            if (i + 1 < N_NODES) { g_rowptr[i + 1] = r1; g_woff[i + 1] = r1; }
            if (i + 2 < N_NODES) { g_rowptr[i + 2] = r2; g_woff[i + 2] = r2; }
            if (i + 3 < N_NODES) { g_rowptr[i + 3] = r3; g_woff[i + 3] = r3; }
        }
        carry += s_w[31];
        __syncthreads();
    }
    if (tid == 0) g_rowptr[N_NODES] = carry;
}

__global__ void k_scatter(const int* __restrict__ ei) {
    int i = blockIdx.x * blockDim.x + threadIdx.x;
    if (i >= E_TOT) return;
    int src, dst;
    if (i < N_EDGES) { src = ei[i]; dst = ei[N_EDGES + i]; }
    else             { src = dst = i - N_EDGES; }
    int pos = atomicAdd(&g_woff[dst], 1);
    g_colsrc[pos] = src;
}

// ---------------- GATConv gather (one warp per node-head) --------------------
// messages gathered from fp16 copy; softmax logits in fp32.
template <int H, bool POOL>
__global__ void k_conv(const __half* __restrict__ hin,
                       const float* __restrict__ as_, const float* __restrict__ ad_,
                       const float* __restrict__ bias, float* __restrict__ hout,
                       const int* __restrict__ batch, float* __restrict__ pooled) {
    int gw = (blockIdx.x * blockDim.x + threadIdx.x) >> 5;
    int lane = threadIdx.x & 31;
    if (gw >= N_NODES * H) return;
    int n = gw / H, h = gw % H;
    int start = g_rowptr[n], end = g_rowptr[n + 1];
    float adn = ad_[n * H + h];

    // pass 1: online softmax stats (lanes over edges)
    float m = -INFINITY, s = 0.f;
    for (int e = start + lane; e < end; e += 32) {
        int src = g_colsrc[e];
        float t = as_[src * H + h] + adn;
        t = (t >= 0.f) ? t : NEG_SLOPE * t;
        if (t > m) { s = s * __expf(m - t); m = t; }
        s += __expf(t - m);
    }
#pragma unroll
    for (int o = 16; o > 0; o >>= 1) {
        float mo = __shfl_xor_sync(0xffffffffu, m, o);
        float so = __shfl_xor_sync(0xffffffffu, s, o);
        float mn = fmaxf(m, mo);
        float s1 = (m > -INFINITY) ? s * __expf(m - mn) : 0.f;
        float s2 = (mo > -INFINITY) ? so * __expf(mo - mn) : 0.f;
        s = s1 + s2; m = mn;
    }
    float inv = 1.f / (s + 1e-16f);

    // pass 2: accumulate (lanes over channels, serial over edges)
    float acc0 = 0.f, acc1 = 0.f;
    for (int e = start; e < end; e++) {
        int src = g_colsrc[e];
        float t = as_[src * H + h] + adn;
        t = (t >= 0.f) ? t : NEG_SLOPE * t;
        float wgt = __expf(t - m) * inv;
        __half2 hv = ((const __half2*)(hin + (size_t)src * (H * HID) + h * HID))[lane];
        float2 v = __half22float2(hv);
        acc0 += v.x * wgt;
        acc1 += v.y * wgt;
    }
    float o0 = acc0 + bias[h * HID + 2 * lane];
    float o1 = acc1 + bias[h * HID + 2 * lane + 1];
    o0 = (o0 > 0.f) ? o0 : expm1f(o0);   // elu
    o1 = (o1 > 0.f) ? o1 : expm1f(o1);
    if (POOL) {
        int g = batch[n];
        float* p0 = &pooled[g * HID + 2 * lane];
        float* p1 = p0 + 1;
        if (o0 >= 0.f) atomicMax((int*)p0, __float_as_int(o0));
        else           atomicMin((unsigned int*)p0, __float_as_uint(o0));
        if (o1 >= 0.f) atomicMax((int*)p1, __float_as_int(o1));
        else           atomicMin((unsigned int*)p1, __float_as_uint(o1));
    } else {
        ((float2*)(hout + (size_t)n * (H * HID) + h * HID))[lane] = make_float2(o0, o1);
    }
}

// ---------------- final FC ---------------------------------------------------
__global__ void k_fc(const float* __restrict__ fcW, const float* __restrict__ fcb,
                     float* __restrict__ out) {
    int i = blockIdx.x * blockDim.x + threadIdx.x;
    if (i >= NUM_GRAPHS * OUT_DIM) return;
    int g = i / OUT_DIM, o = i % OUT_DIM;
    float acc = fcb[o];
#pragma unroll
    for (int c = 0; c < HID; c++)
        acc += g_pooled[g * HID + c] * fcW[o * HID + c];
    out[i] = acc;
}

// ---------------- launch -----------------------------------------------------
extern "C" void kernel_launch(void* const* d_in, const int* in_sizes, int n_in,
                              void* d_out, int out_size) {
    const float* x      = (const float*)d_in[0];
    const int*   ei     = (const int*)  d_in[1];
    const int*   batch  = (const int*)  d_in[2];
    const float* W1     = (const float*)d_in[3];
    const float* a_src1 = (const float*)d_in[4];
    const float* a_dst1 = (const float*)d_in[5];
    const float* b1     = (const float*)d_in[6];
    const float* W2     = (const float*)d_in[7];
    const float* a_src2 = (const float*)d_in[8];
    const float* a_dst2 = (const float*)d_in[9];
    const float* b2     = (const float*)d_in[10];
    const float* fcW    = (const float*)d_in[11];
    const float* fcb    = (const float*)d_in[12];
    float* out = (float*)d_out;

    float *h1, *h1o, *h2, *as1, *ad1, *as2, *ad2, *pooled;
    __half *h1h, *h2h;
    cudaGetSymbolAddress((void**)&h1,   g_h1);
    cudaGetSymbolAddress((void**)&h1h,  g_h1h);
    cudaGetSymbolAddress((void**)&h1o,  g_h1o);
    cudaGetSymbolAddress((void**)&h2,   g_h2);
    cudaGetSymbolAddress((void**)&h2h,  g_h2h);
    cudaGetSymbolAddress((void**)&as1,  g_as1);
    cudaGetSymbolAddress((void**)&ad1,  g_ad1);
    cudaGetSymbolAddress((void**)&as2,  g_as2);
    cudaGetSymbolAddress((void**)&ad2,  g_ad2);
    cudaGetSymbolAddress((void**)&pooled, g_pooled);

    const int B = 256;

    k_init<<<(N_NODES + B - 1) / B, B>>>();

    // CSR build (reused by both layers)
    k_deg<<<(E_TOT + B - 1) / B, B>>>(ei);
    k_scan<<<1, 1024>>>();
    k_scatter<<<(E_TOT + B - 1) / B, B>>>(ei);

    // layer 1
    {
        dim3 grid((HEADS * HID) / 128, (N_NODES + 127) / 128);
        k_gemm<128><<<grid, 256>>>(x, W1, h1, h1h, N_NODES, HEADS * HID, IN_DIM);
    }
    k_alpha<HEADS><<<(N_NODES * HEADS * 32 + B - 1) / B, B>>>(h1, a_src1, a_dst1, as1, ad1);
    k_conv<HEADS, false><<<(N_NODES * HEADS * 32 + B - 1) / B, B>>>(
        h1h, as1, ad1, b1, h1o, nullptr, nullptr);

    // layer 2
    {
        dim3 grid(HID / 64, (N_NODES + 127) / 128);
        k_gemm<64><<<grid, 128>>>(h1o, W2, h2, h2h, N_NODES, HID, HEADS * HID);
    }
    k_alpha<1><<<(N_NODES * 32 + B - 1) / B, B>>>(h2, a_src2, a_dst2, as2, ad2);
    k_conv<1, true><<<(N_NODES * 32 + B - 1) / B, B>>>(
        h2h, as2, ad2, b2, nullptr, batch, pooled);

    // fc
    k_fc<<<(NUM_GRAPHS * OUT_DIM + B - 1) / B, B>>>(fcW, fcb, out);
}

// round 3
// speedup vs baseline: 1.1645x; 1.1645x over previous
#include <cuda_runtime.h>
#include <cuda_fp16.h>
#include <math.h>

#define N_NODES 50000
#define N_EDGES 800000
#define E_TOT   (N_EDGES + N_NODES)
#define IN_DIM  128
#define HID     64
#define HEADS   4
#define OUT_DIM 20
#define NUM_GRAPHS 64
#define NEG_SLOPE 0.2f

// ---------------- scratch (static device globals; no allocation) -------------
__device__ __half g_h1h [N_NODES * HEADS * HID];   // x @ W1^T (fp16)
__device__ float  g_h1o [N_NODES * HEADS * HID];   // elu(conv1 out) fp32 (GEMM2 A)
__device__ __half g_h2h [N_NODES * HID];           // h1o @ W2^T (fp16)
__device__ float  g_as1 [N_NODES * HEADS];
__device__ float  g_ad1 [N_NODES * HEADS];
__device__ float  g_as2 [N_NODES];
__device__ float  g_ad2 [N_NODES];
__device__ int    g_deg   [N_NODES];
__device__ int    g_rowptr[N_NODES + 1];
__device__ int    g_woff  [N_NODES];
__device__ int    g_colsrc[E_TOT];
__device__ float  g_pooled[NUM_GRAPHS * HID];

// ---------------- f32x2 packed-FMA helpers (sm_103a) -------------------------
__device__ __forceinline__ void fma2(unsigned long long& d,
                                     unsigned long long a, unsigned long long b) {
    asm("fma.rn.f32x2 %0, %1, %2, %0;" : "+l"(d) : "l"(a), "l"(b));
}
__device__ __forceinline__ unsigned long long pack2(float x, float y) {
    unsigned long long r;
    asm("mov.b64 %0, {%1, %2};" : "=l"(r) : "f"(x), "f"(y));
    return r;
}
__device__ __forceinline__ void unpack2(unsigned long long v, float& x, float& y) {
    asm("mov.b64 {%0, %1}, %2;" : "=f"(x), "=f"(y) : "l"(v));
}

// ---------------- init ------------------------------------------------------
__global__ void k_init() {
    int i = blockIdx.x * blockDim.x + threadIdx.x;
    if (i < N_NODES) g_deg[i] = 0;
    if (i < NUM_GRAPHS * HID) ((int*)g_pooled)[i] = 0xFF800000; // -inf
}

// ---------------- SGEMM (NT) with packed f32x2; fp16 output ------------------
// Ch[M,N] = half(A[M,K] * B[N,K]^T).  BM=128, BK=16, microtile 8x8.
template <int BN>
__global__ void k_gemm(const float* __restrict__ A, const float* __restrict__ B,
                       __half* __restrict__ Ch, int M, int N, int K) {
    constexpr int BM = 128, BK = 16;
    constexpr int NT = 16 * (BN / 8);
    __shared__ float As[BK][BM];
    __shared__ float Bs[BK][BN];
    int tid = threadIdx.x;
    int tx = tid % (BN / 8), ty = tid / (BN / 8);
    int row0 = blockIdx.y * BM, col0 = blockIdx.x * BN;

    unsigned long long acc[8][4];
#pragma unroll
    for (int i = 0; i < 8; i++)
#pragma unroll
        for (int j = 0; j < 4; j++) acc[i][j] = 0ULL;

    for (int k0 = 0; k0 < K; k0 += BK) {
#pragma unroll
        for (int i = 0; i < (BM * 4) / NT; i++) {
            int idx = tid + i * NT;
            int r = idx >> 2, kc = (idx & 3) * 4;
            int ar = row0 + r;
            float4 v = (ar < M) ? *(const float4*)(A + (size_t)ar * K + k0 + kc)
                                : make_float4(0.f, 0.f, 0.f, 0.f);
            As[kc + 0][r] = v.x; As[kc + 1][r] = v.y;
            As[kc + 2][r] = v.z; As[kc + 3][r] = v.w;
        }
#pragma unroll
        for (int i = 0; i < (BN * 4) / NT; i++) {
            int idx = tid + i * NT;
            int r = idx >> 2, kc = (idx & 3) * 4;
            float4 v = *(const float4*)(B + (size_t)(col0 + r) * K + k0 + kc);
            Bs[kc + 0][r] = v.x; Bs[kc + 1][r] = v.y;
            Bs[kc + 2][r] = v.z; Bs[kc + 3][r] = v.w;
        }
        __syncthreads();
#pragma unroll
        for (int kk = 0; kk < BK; kk++) {
            float4 a0 = *(const float4*)&As[kk][ty * 8];
            float4 a1 = *(const float4*)&As[kk][ty * 8 + 4];
            float4 b0 = *(const float4*)&Bs[kk][tx * 8];
            float4 b1 = *(const float4*)&Bs[kk][tx * 8 + 4];
            unsigned long long bp[4] = {pack2(b0.x, b0.y), pack2(b0.z, b0.w),
                                        pack2(b1.x, b1.y), pack2(b1.z, b1.w)};
            float ar8[8] = {a0.x, a0.y, a0.z, a0.w, a1.x, a1.y, a1.z, a1.w};
#pragma unroll
            for (int i = 0; i < 8; i++) {
                unsigned long long ap = pack2(ar8[i], ar8[i]);
                fma2(acc[i][0], ap, bp[0]);
                fma2(acc[i][1], ap, bp[1]);
                fma2(acc[i][2], ap, bp[2]);
                fma2(acc[i][3], ap, bp[3]);
            }
        }
        __syncthreads();
    }
#pragma unroll
    for (int i = 0; i < 8; i++) {
        int r = row0 + ty * 8 + i;
        if (r >= M) continue;
        float o[8];
#pragma unroll
        for (int j = 0; j < 4; j++) unpack2(acc[i][j], o[2 * j], o[2 * j + 1]);
        __align__(16) __half2 hh[4];
#pragma unroll
        for (int j = 0; j < 4; j++) hh[j] = __floats2half2_rn(o[2 * j], o[2 * j + 1]);
        *(float4*)(Ch + (size_t)r * N + col0 + tx * 8) = *(float4*)hh;
    }
}

// ---------------- alpha dots from fp16 h (one warp per node-head) ------------
template <int H>
__global__ void k_alpha(const __half* __restrict__ hlin,
                        const float* __restrict__ a_s, const float* __restrict__ a_d,
                        float* __restrict__ as_o, float* __restrict__ ad_o) {
    int gw = (blockIdx.x * blockDim.x + threadIdx.x) >> 5;
    int lane = threadIdx.x & 31;
    if (gw >= N_NODES * H) return;
    int n = gw / H, h = gw % H;
    __half2 hraw = ((const __half2*)(hlin + (size_t)n * H * HID + h * HID))[lane];
    float2 hv = __half22float2(hraw);
    float2 sv = ((const float2*)(a_s + h * HID))[lane];
    float2 dv = ((const float2*)(a_d + h * HID))[lane];
    float s = hv.x * sv.x + hv.y * sv.y;
    float d = hv.x * dv.x + hv.y * dv.y;
#pragma unroll
    for (int o = 16; o > 0; o >>= 1) {
        s += __shfl_xor_sync(0xffffffffu, s, o);
        d += __shfl_xor_sync(0xffffffffu, d, o);
    }
    if (lane == 0) { as_o[gw] = s; ad_o[gw] = d; }
}

// ---------------- CSR build --------------------------------------------------
__global__ void k_deg(const int* __restrict__ ei) {
    int i = blockIdx.x * blockDim.x + threadIdx.x;
    if (i >= E_TOT) return;
    int dst = (i < N_EDGES) ? ei[N_EDGES + i] : (i - N_EDGES);
    atomicAdd(&g_deg[dst], 1);
}

__global__ void k_scan() {   // single block, 1024 threads, 4 elems/thread/iter
    __shared__ int s_w[32];
    int tid = threadIdx.x, lane = tid & 31, w = tid >> 5;
    int carry = 0;
    for (int base = 0; base < N_NODES; base += 4096) {
        int i = base + tid * 4;
        int a0 = 0, a1 = 0, a2 = 0, a3 = 0;
        if (i + 3 < N_NODES) {
            int4 v = *(const int4*)&g_deg[i];
            a0 = v.x; a1 = v.y; a2 = v.z; a3 = v.w;
        } else {
            if (i     < N_NODES) a0 = g_deg[i];
            if (i + 1 < N_NODES) a1 = g_deg[i + 1];
            if (i + 2 < N_NODES) a2 = g_deg[i + 2];
            if (i + 3 < N_NODES) a3 = g_deg[i + 3];
        }
        int t = a0 + a1 + a2 + a3;
        int x = t;
#pragma unroll
        for (int o = 1; o < 32; o <<= 1) {
            int u = __shfl_up_sync(0xffffffffu, x, o);
            if (lane >= o) x += u;
        }
        if (lane == 31) s_w[w] = x;
        __syncthreads();
        if (w == 0) {
            int y = s_w[lane];
#pragma unroll
            for (int o = 1; o < 32; o <<= 1) {
                int u = __shfl_up_sync(0xffffffffu, y, o);
                if (lane >= o) y += u;
            }
            s_w[lane] = y;
        }
        __syncthreads();
        int excl = carry + (w ? s_w[w - 1] : 0) + (x - t);
        int r0 = excl, r1 = excl + a0, r2 = r1 + a1, r3 = r2 + a2;
        if (i + 3 < N_NODES) {
            *(int4*)&g_rowptr[i] = make_int4(r0, r1, r2, r3);
            *(int4*)&g_woff[i]   = make_int4(r0, r1, r2, r3);
        } else {
            if (i     < N_NODES) { g_rowptr[i]     = r0; g_woff[i]     = r0; }
            if (i + 1 < N_NODES) { g_rowptr[i + 1] = r1; g_woff[i + 1] = r1; }
            if (i + 2 < N_NODES) { g_rowptr[i + 2] = r2; g_woff[i + 2] = r2; }
            if (i + 3 < N_NODES) { g_rowptr[i + 3] = r3; g_woff[i + 3] = r3; }
        }
        carry += s_w[31];
        __syncthreads();
    }
    if (tid == 0) g_rowptr[N_NODES] = carry;
}

__global__ void k_scatter(const int* __restrict__ ei) {
    int i = blockIdx.x * blockDim.x + threadIdx.x;
    if (i >= E_TOT) return;
    int src, dst;
    if (i < N_EDGES) { src = ei[i]; dst = ei[N_EDGES + i]; }
    else             { src = dst = i - N_EDGES; }
    int pos = atomicAdd(&g_woff[dst], 1);
    g_colsrc[pos] = src;
}

// ---------------- GATConv gather: single pass, tile-parallel weights ---------
// No max-subtraction (logits bounded, exp safe in fp32). Each warp handles one
// (node,head). Per 32-edge tile: each lane computes one edge's exp-weight in
// parallel (overlapping the random alpha loads); then an inner loop broadcasts
// (src, w) via shfl and does a coalesced 128B gather of h[src] — loads are
// independent across iterations -> high MLP.
template <int H, bool POOL>
__global__ void k_conv(const __half* __restrict__ hin,
                       const float* __restrict__ as_, const float* __restrict__ ad_,
                       const float* __restrict__ bias, float* __restrict__ hout,
                       const int* __restrict__ batch, float* __restrict__ pooled) {
    int gw = (blockIdx.x * blockDim.x + threadIdx.x) >> 5;
    int lane = threadIdx.x & 31;
    if (gw >= N_NODES * H) return;
    int n = gw / H, h = gw % H;
    int start = g_rowptr[n], end = g_rowptr[n + 1];
    float adn = ad_[n * H + h];

    float wsum = 0.f;
    float acc0 = 0.f, acc1 = 0.f;
    const __half2* hbase = (const __half2*)(hin + (size_t)h * HID) + lane;

    for (int tile = start; tile < end; tile += 32) {
        int e = tile + lane;
        int s = 0;
        float w = 0.f;
        if (e < end) {
            s = g_colsrc[e];
            float t = as_[s * H + h] + adn;
            t = (t >= 0.f) ? t : NEG_SLOPE * t;
            w = __expf(t);
        }
        wsum += w;
        int cnt = min(32, end - tile);
        for (int j = 0; j < cnt; j++) {
            int src  = __shfl_sync(0xffffffffu, s, j);
            float wj = __shfl_sync(0xffffffffu, w, j);
            __half2 hv = hbase[(size_t)src * (H * HID / 2)];
            float2 v = __half22float2(hv);
            acc0 += v.x * wj;
            acc1 += v.y * wj;
        }
    }
#pragma unroll
    for (int o = 16; o > 0; o >>= 1)
        wsum += __shfl_xor_sync(0xffffffffu, wsum, o);
    float inv = 1.f / (wsum + 1e-16f);

    float o0 = acc0 * inv + bias[h * HID + 2 * lane];
    float o1 = acc1 * inv + bias[h * HID + 2 * lane + 1];
    o0 = (o0 > 0.f) ? o0 : expm1f(o0);   // elu
    o1 = (o1 > 0.f) ? o1 : expm1f(o1);
    if (POOL) {
        int g = batch[n];
        float* p0 = &pooled[g * HID + 2 * lane];
        float* p1 = p0 + 1;
        if (o0 >= 0.f) atomicMax((int*)p0, __float_as_int(o0));
        else           atomicMin((unsigned int*)p0, __float_as_uint(o0));
        if (o1 >= 0.f) atomicMax((int*)p1, __float_as_int(o1));
        else           atomicMin((unsigned int*)p1, __float_as_uint(o1));
    } else {
        ((float2*)(hout + (size_t)n * (H * HID) + h * HID))[lane] = make_float2(o0, o1);
    }
}

// ---------------- final FC ---------------------------------------------------
__global__ void k_fc(const float* __restrict__ fcW, const float* __restrict__ fcb,
                     float* __restrict__ out) {
    int i = blockIdx.x * blockDim.x + threadIdx.x;
    if (i >= NUM_GRAPHS * OUT_DIM) return;
    int g = i / OUT_DIM, o = i % OUT_DIM;
    float acc = fcb[o];
#pragma unroll
    for (int c = 0; c < HID; c++)
        acc += g_pooled[g * HID + c] * fcW[o * HID + c];
    out[i] = acc;
}

// ---------------- launch -----------------------------------------------------
extern "C" void kernel_launch(void* const* d_in, const int* in_sizes, int n_in,
                              void* d_out, int out_size) {
    const float* x      = (const float*)d_in[0];
    const int*   ei     = (const int*)  d_in[1];
    const int*   batch  = (const int*)  d_in[2];
    const float* W1     = (const float*)d_in[3];
    const float* a_src1 = (const float*)d_in[4];
    const float* a_dst1 = (const float*)d_in[5];
    const float* b1     = (const float*)d_in[6];
    const float* W2     = (const float*)d_in[7];
    const float* a_src2 = (const float*)d_in[8];
    const float* a_dst2 = (const float*)d_in[9];
    const float* b2     = (const float*)d_in[10];
    const float* fcW    = (const float*)d_in[11];
    const float* fcb    = (const float*)d_in[12];
    float* out = (float*)d_out;

    float *h1o, *as1, *ad1, *as2, *ad2, *pooled;
    __half *h1h, *h2h;
    cudaGetSymbolAddress((void**)&h1h,  g_h1h);
    cudaGetSymbolAddress((void**)&h1o,  g_h1o);
    cudaGetSymbolAddress((void**)&h2h,  g_h2h);
    cudaGetSymbolAddress((void**)&as1,  g_as1);
    cudaGetSymbolAddress((void**)&ad1,  g_ad1);
    cudaGetSymbolAddress((void**)&as2,  g_as2);
    cudaGetSymbolAddress((void**)&ad2,  g_ad2);
    cudaGetSymbolAddress((void**)&pooled, g_pooled);

    const int B = 256;

    k_init<<<(N_NODES + B - 1) / B, B>>>();

    // CSR build (reused by both layers)
    k_deg<<<(E_TOT + B - 1) / B, B>>>(ei);
    k_scan<<<1, 1024>>>();
    k_scatter<<<(E_TOT + B - 1) / B, B>>>(ei);

    // layer 1
    {
        dim3 grid((HEADS * HID) / 128, (N_NODES + 127) / 128);
        k_gemm<128><<<grid, 256>>>(x, W1, h1h, N_NODES, HEADS * HID, IN_DIM);
    }
    k_alpha<HEADS><<<(N_NODES * HEADS * 32 + B - 1) / B, B>>>(h1h, a_src1, a_dst1, as1, ad1);
    k_conv<HEADS, false><<<(N_NODES * HEADS * 32 + B - 1) / B, B>>>(
        h1h, as1, ad1, b1, h1o, nullptr, nullptr);

    // layer 2
    {
        dim3 grid(HID / 64, (N_NODES + 127) / 128);
        k_gemm<64><<<grid, 128>>>(h1o, W2, h2h, N_NODES, HID, HEADS * HID);
    }
    k_alpha<1><<<(N_NODES * 32 + B - 1) / B, B>>>(h2h, a_src2, a_dst2, as2, ad2);
    k_conv<1, true><<<(N_NODES * 32 + B - 1) / B, B>>>(
        h2h, as2, ad2, b2, nullptr, batch, pooled);

    // fc
    k_fc<<<(NUM_GRAPHS * OUT_DIM + B - 1) / B, B>>>(fcW, fcb, out);
}

// round 4
// speedup vs baseline: 1.4871x; 1.2770x over previous
#include <cuda_runtime.h>
#include <cuda_fp16.h>
#include <mma.h>
#include <math.h>

using namespace nvcuda;

#define N_NODES 50000
#define M_PAD   50048              // 391 * 128
#define N_EDGES 800000
#define E_TOT   (N_EDGES + N_NODES)
#define IN_DIM  128
#define HID     64
#define HEADS   4
#define OUT_DIM 20
#define NUM_GRAPHS 64
#define NEG_SLOPE 0.2f

// ---------------- scratch (static device globals; no allocation) -------------
__device__ __half g_xh  [M_PAD * IN_DIM];          // x in fp16 (pad rows = 0)
__device__ __half g_w1h [HEADS * HID * IN_DIM];    // W1 fp16
__device__ __half g_w2h [HID * HEADS * HID];       // W2 fp16
__device__ __half g_h1h [M_PAD * HEADS * HID];     // x @ W1^T (fp16)
__device__ __half g_h1oh[M_PAD * HEADS * HID];     // elu(conv1) fp16 (GEMM2 A; pad rows stay 0)
__device__ __half g_h2h [M_PAD * HID];             // h1o @ W2^T (fp16)
__device__ float  g_as1 [N_NODES * HEADS];
__device__ float  g_ad1 [N_NODES * HEADS];
__device__ float  g_as2 [N_NODES];
__device__ float  g_ad2 [N_NODES];
__device__ int    g_deg   [N_NODES];
__device__ int    g_rowptr[N_NODES + 1];
__device__ int    g_woff  [N_NODES];
__device__ int    g_colsrc[E_TOT];
__device__ float  g_pooled[NUM_GRAPHS * HID];

// ---------------- init ------------------------------------------------------
__global__ void k_init() {
    int i = blockIdx.x * blockDim.x + threadIdx.x;
    if (i < N_NODES) g_deg[i] = 0;
    if (i < NUM_GRAPHS * HID) ((int*)g_pooled)[i] = 0xFF800000; // -inf
}

// ---------------- fp32 -> fp16 convert (zero-fills [n_valid, n_total)) -------
__global__ void k_tohalf(const float* __restrict__ src, __half* __restrict__ dst,
                         int n_valid, int n_total) {
    int i = (blockIdx.x * blockDim.x + threadIdx.x) * 4;
    if (i >= n_total) return;
    float4 v;
    if (i + 3 < n_valid) {
        v = *(const float4*)(src + i);
    } else {
        v.x = (i     < n_valid) ? src[i]     : 0.f;
        v.y = (i + 1 < n_valid) ? src[i + 1] : 0.f;
        v.z = (i + 2 < n_valid) ? src[i + 2] : 0.f;
        v.w = (i + 3 < n_valid) ? src[i + 3] : 0.f;
    }
    __half2 h0 = __floats2half2_rn(v.x, v.y);
    __half2 h1 = __floats2half2_rn(v.z, v.w);
    uint2 p;
    p.x = *(unsigned int*)&h0;
    p.y = *(unsigned int*)&h1;
    *(uint2*)(dst + i) = p;
}

// ---------------- HGEMM (NT) via wmma: Ch[M,N] = half(A[M,K] @ B[N,K]^T) -----
// Block tile 128x64, 8 warps (4x2), warp tile 32x32 (2x2 wmma 16x16x16), BK=64.
// M must be a multiple of 128 (buffers padded), N of 64, K of 64. No guards.
__global__ void k_gemm_h(const __half* __restrict__ A, const __half* __restrict__ B,
                         __half* __restrict__ C, int M, int N, int K) {
    __shared__ __half As[128][72];
    __shared__ __half Bs[64][72];
    int tid = threadIdx.x;
    int wid = tid >> 5;
    int wr = wid >> 1;   // 0..3
    int wc = wid & 1;    // 0..1
    int row0 = blockIdx.y * 128;
    int col0 = blockIdx.x * 64;

    wmma::fragment<wmma::accumulator, 16, 16, 16, float> c[2][2];
#pragma unroll
    for (int i = 0; i < 2; i++)
#pragma unroll
        for (int j = 0; j < 2; j++) wmma::fill_fragment(c[i][j], 0.f);

    for (int k0 = 0; k0 < K; k0 += 64) {
#pragma unroll
        for (int l = 0; l < 4; l++) {
            int chunk = tid + l * 256;          // 0..1023
            int r = chunk >> 3;
            int c8 = (chunk & 7) * 8;
            *(uint4*)&As[r][c8] = *(const uint4*)(A + (size_t)(row0 + r) * K + k0 + c8);
        }
#pragma unroll
        for (int l = 0; l < 2; l++) {
            int chunk = tid + l * 256;          // 0..511
            int r = chunk >> 3;
            int c8 = (chunk & 7) * 8;
            *(uint4*)&Bs[r][c8] = *(const uint4*)(B + (size_t)(col0 + r) * K + k0 + c8);
        }
        __syncthreads();
#pragma unroll
        for (int kk = 0; kk < 64; kk += 16) {
            wmma::fragment<wmma::matrix_a, 16, 16, 16, __half, wmma::row_major> a0, a1;
            wmma::fragment<wmma::matrix_b, 16, 16, 16, __half, wmma::col_major> b0, b1;
            wmma::load_matrix_sync(a0, &As[wr * 32][kk], 72);
            wmma::load_matrix_sync(a1, &As[wr * 32 + 16][kk], 72);
            wmma::load_matrix_sync(b0, &Bs[wc * 32][kk], 72);
            wmma::load_matrix_sync(b1, &Bs[wc * 32 + 16][kk], 72);
            wmma::mma_sync(c[0][0], a0, b0, c[0][0]);
            wmma::mma_sync(c[0][1], a0, b1, c[0][1]);
            wmma::mma_sync(c[1][0], a1, b0, c[1][0]);
            wmma::mma_sync(c[1][1], a1, b1, c[1][1]);
        }
        __syncthreads();
    }
#pragma unroll
    for (int i = 0; i < 2; i++)
#pragma unroll
        for (int j = 0; j < 2; j++) {
            wmma::fragment<wmma::accumulator, 16, 16, 16, __half> hc;
#pragma unroll
            for (int e = 0; e < hc.num_elements; e++)
                hc.x[e] = __float2half(c[i][j].x[e]);
            wmma::store_matrix_sync(
                C + (size_t)(row0 + wr * 32 + i * 16) * N + col0 + wc * 32 + j * 16,
                hc, N, wmma::mem_row_major);
        }
}

// ---------------- alpha dots from fp16 h (one warp per node-head) ------------
template <int H>
__global__ void k_alpha(const __half* __restrict__ hlin,
                        const float* __restrict__ a_s, const float* __restrict__ a_d,
                        float* __restrict__ as_o, float* __restrict__ ad_o) {
    int gw = (blockIdx.x * blockDim.x + threadIdx.x) >> 5;
    int lane = threadIdx.x & 31;
    if (gw >= N_NODES * H) return;
    int n = gw / H, h = gw % H;
    __half2 hraw = ((const __half2*)(hlin + (size_t)n * H * HID + h * HID))[lane];
    float2 hv = __half22float2(hraw);
    float2 sv = ((const float2*)(a_s + h * HID))[lane];
    float2 dv = ((const float2*)(a_d + h * HID))[lane];
    float s = hv.x * sv.x + hv.y * sv.y;
    float d = hv.x * dv.x + hv.y * dv.y;
#pragma unroll
    for (int o = 16; o > 0; o >>= 1) {
        s += __shfl_xor_sync(0xffffffffu, s, o);
        d += __shfl_xor_sync(0xffffffffu, d, o);
    }
    if (lane == 0) { as_o[gw] = s; ad_o[gw] = d; }
}

// ---------------- CSR build --------------------------------------------------
__global__ void k_deg(const int* __restrict__ ei) {
    int i = blockIdx.x * blockDim.x + threadIdx.x;
    if (i >= E_TOT) return;
    int dst = (i < N_EDGES) ? ei[N_EDGES + i] : (i - N_EDGES);
    atomicAdd(&g_deg[dst], 1);
}

__global__ void k_scan() {   // single block, 1024 threads, 4 elems/thread/iter
    __shared__ int s_w[32];
    int tid = threadIdx.x, lane = tid & 31, w = tid >> 5;
    int carry = 0;
    for (int base = 0; base < N_NODES; base += 4096) {
        int i = base + tid * 4;
        int a0 = 0, a1 = 0, a2 = 0, a3 = 0;
        if (i + 3 < N_NODES) {
            int4 v = *(const int4*)&g_deg[i];
            a0 = v.x; a1 = v.y; a2 = v.z; a3 = v.w;
        } else {
            if (i     < N_NODES) a0 = g_deg[i];
            if (i + 1 < N_NODES) a1 = g_deg[i + 1];
            if (i + 2 < N_NODES) a2 = g_deg[i + 2];
            if (i + 3 < N_NODES) a3 = g_deg[i + 3];
        }
        int t = a0 + a1 + a2 + a3;
        int x = t;
#pragma unroll
        for (int o = 1; o < 32; o <<= 1) {
            int u = __shfl_up_sync(0xffffffffu, x, o);
            if (lane >= o) x += u;
        }
        if (lane == 31) s_w[w] = x;
        __syncthreads();
        if (w == 0) {
            int y = s_w[lane];
#pragma unroll
            for (int o = 1; o < 32; o <<= 1) {
                int u = __shfl_up_sync(0xffffffffu, y, o);
                if (lane >= o) y += u;
            }
            s_w[lane] = y;
        }
        __syncthreads();
        int excl = carry + (w ? s_w[w - 1] : 0) + (x - t);
        int r0 = excl, r1 = excl + a0, r2 = r1 + a1, r3 = r2 + a2;
        if (i + 3 < N_NODES) {
            *(int4*)&g_rowptr[i] = make_int4(r0, r1, r2, r3);
            *(int4*)&g_woff[i]   = make_int4(r0, r1, r2, r3);
        } else {
            if (i     < N_NODES) { g_rowptr[i]     = r0; g_woff[i]     = r0; }
            if (i + 1 < N_NODES) { g_rowptr[i + 1] = r1; g_woff[i + 1] = r1; }
            if (i + 2 < N_NODES) { g_rowptr[i + 2] = r2; g_woff[i + 2] = r2; }
            if (i + 3 < N_NODES) { g_rowptr[i + 3] = r3; g_woff[i + 3] = r3; }
        }
        carry += s_w[31];
        __syncthreads();
    }
    if (tid == 0) g_rowptr[N_NODES] = carry;
}

__global__ void k_scatter(const int* __restrict__ ei) {
    int i = blockIdx.x * blockDim.x + threadIdx.x;
    if (i >= E_TOT) return;
    int src, dst;
    if (i < N_EDGES) { src = ei[i]; dst = ei[N_EDGES + i]; }
    else             { src = dst = i - N_EDGES; }
    int pos = atomicAdd(&g_woff[dst], 1);
    g_colsrc[pos] = src;
}

// ---------------- GATConv gather: single pass, tile-parallel weights ---------
template <int H, bool POOL>
__global__ void k_conv(const __half* __restrict__ hin,
                       const float* __restrict__ as_, const float* __restrict__ ad_,
                       const float* __restrict__ bias, __half* __restrict__ hout,
                       const int* __restrict__ batch, float* __restrict__ pooled) {
    int gw = (blockIdx.x * blockDim.x + threadIdx.x) >> 5;
    int lane = threadIdx.x & 31;
    if (gw >= N_NODES * H) return;
    int n = gw / H, h = gw % H;
    int start = g_rowptr[n], end = g_rowptr[n + 1];
    float adn = ad_[n * H + h];

    float wsum = 0.f;
    float acc0 = 0.f, acc1 = 0.f;
    const __half2* hbase = (const __half2*)(hin + (size_t)h * HID) + lane;

    for (int tile = start; tile < end; tile += 32) {
        int e = tile + lane;
        int s = 0;
        float w = 0.f;
        if (e < end) {
            s = g_colsrc[e];
            float t = as_[s * H + h] + adn;
            t = (t >= 0.f) ? t : NEG_SLOPE * t;
            w = __expf(t);
        }
        wsum += w;
        int cnt = min(32, end - tile);
        for (int j = 0; j < cnt; j++) {
            int src  = __shfl_sync(0xffffffffu, s, j);
            float wj = __shfl_sync(0xffffffffu, w, j);
            __half2 hv = hbase[(size_t)src * (H * HID / 2)];
            float2 v = __half22float2(hv);
            acc0 += v.x * wj;
            acc1 += v.y * wj;
        }
    }
#pragma unroll
    for (int o = 16; o > 0; o >>= 1)
        wsum += __shfl_xor_sync(0xffffffffu, wsum, o);
    float inv = 1.f / (wsum + 1e-16f);

    float o0 = acc0 * inv + bias[h * HID + 2 * lane];
    float o1 = acc1 * inv + bias[h * HID + 2 * lane + 1];
    o0 = (o0 > 0.f) ? o0 : expm1f(o0);   // elu
    o1 = (o1 > 0.f) ? o1 : expm1f(o1);
    if (POOL) {
        int g = batch[n];
        float* p0 = &pooled[g * HID + 2 * lane];
        float* p1 = p0 + 1;
        if (o0 >= 0.f) atomicMax((int*)p0, __float_as_int(o0));
        else           atomicMin((unsigned int*)p0, __float_as_uint(o0));
        if (o1 >= 0.f) atomicMax((int*)p1, __float_as_int(o1));
        else           atomicMin((unsigned int*)p1, __float_as_uint(o1));
    } else {
        ((__half2*)(hout + (size_t)n * (H * HID) + h * HID))[lane] =
            __floats2half2_rn(o0, o1);
    }
}

// ---------------- final FC ---------------------------------------------------
__global__ void k_fc(const float* __restrict__ fcW, const float* __restrict__ fcb,
                     float* __restrict__ out) {
    int i = blockIdx.x * blockDim.x + threadIdx.x;
    if (i >= NUM_GRAPHS * OUT_DIM) return;
    int g = i / OUT_DIM, o = i % OUT_DIM;
    float acc = fcb[o];
#pragma unroll
    for (int c = 0; c < HID; c++)
        acc += g_pooled[g * HID + c] * fcW[o * HID + c];
    out[i] = acc;
}

// ---------------- launch -----------------------------------------------------
extern "C" void kernel_launch(void* const* d_in, const int* in_sizes, int n_in,
                              void* d_out, int out_size) {
    const float* x      = (const float*)d_in[0];
    const int*   ei     = (const int*)  d_in[1];
    const int*   batch  = (const int*)  d_in[2];
    const float* W1     = (const float*)d_in[3];
    const float* a_src1 = (const float*)d_in[4];
    const float* a_dst1 = (const float*)d_in[5];
    const float* b1     = (const float*)d_in[6];
    const float* W2     = (const float*)d_in[7];
    const float* a_src2 = (const float*)d_in[8];
    const float* a_dst2 = (const float*)d_in[9];
    const float* b2     = (const float*)d_in[10];
    const float* fcW    = (const float*)d_in[11];
    const float* fcb    = (const float*)d_in[12];
    float* out = (float*)d_out;

    __half *xh, *w1h, *w2h, *h1h, *h1oh, *h2h;
    float *as1, *ad1, *as2, *ad2, *pooled;
    cudaGetSymbolAddress((void**)&xh,   g_xh);
    cudaGetSymbolAddress((void**)&w1h,  g_w1h);
    cudaGetSymbolAddress((void**)&w2h,  g_w2h);
    cudaGetSymbolAddress((void**)&h1h,  g_h1h);
    cudaGetSymbolAddress((void**)&h1oh, g_h1oh);
    cudaGetSymbolAddress((void**)&h2h,  g_h2h);
    cudaGetSymbolAddress((void**)&as1,  g_as1);
    cudaGetSymbolAddress((void**)&ad1,  g_ad1);
    cudaGetSymbolAddress((void**)&as2,  g_as2);
    cudaGetSymbolAddress((void**)&ad2,  g_ad2);
    cudaGetSymbolAddress((void**)&pooled, g_pooled);

    const int B = 256;

    k_init<<<(N_NODES + B - 1) / B, B>>>();

    // fp16 conversions
    k_tohalf<<<(M_PAD * IN_DIM / 4 + B - 1) / B, B>>>(
        x, xh, N_NODES * IN_DIM, M_PAD * IN_DIM);
    k_tohalf<<<(HEADS * HID * IN_DIM / 4 + B - 1) / B, B>>>(
        W1, w1h, HEADS * HID * IN_DIM, HEADS * HID * IN_DIM);
    k_tohalf<<<(HID * HEADS * HID / 4 + B - 1) / B, B>>>(
        W2, w2h, HID * HEADS * HID, HID * HEADS * HID);

    // CSR build (reused by both layers)
    k_deg<<<(E_TOT + B - 1) / B, B>>>(ei);
    k_scan<<<1, 1024>>>();
    k_scatter<<<(E_TOT + B - 1) / B, B>>>(ei);

    // layer 1: HGEMM -> alpha -> conv (writes fp16 h1o)
    {
        dim3 grid((HEADS * HID) / 64, M_PAD / 128);
        k_gemm_h<<<grid, 256>>>(xh, w1h, h1h, M_PAD, HEADS * HID, IN_DIM);
    }
    k_alpha<HEADS><<<(N_NODES * HEADS * 32 + B - 1) / B, B>>>(h1h, a_src1, a_dst1, as1, ad1);
    k_conv<HEADS, false><<<(N_NODES * HEADS * 32 + B - 1) / B, B>>>(
        h1h, as1, ad1, b1, h1oh, nullptr, nullptr);

    // layer 2
    {
        dim3 grid(HID / 64, M_PAD / 128);
        k_gemm_h<<<grid, 256>>>(h1oh, w2h, h2h, M_PAD, HID, HEADS * HID);
    }
    k_alpha<1><<<(N_NODES * 32 + B - 1) / B, B>>>(h2h, a_src2, a_dst2, as2, ad2);
    k_conv<1, true><<<(N_NODES * 32 + B - 1) / B, B>>>(
        h2h, as2, ad2, b2, nullptr, batch, pooled);

    // fc
    k_fc<<<(NUM_GRAPHS * OUT_DIM + B - 1) / B, B>>>(fcW, fcb, out);
}

// round 5
// speedup vs baseline: 1.7545x; 1.1798x over previous
#include <cuda_runtime.h>
#include <cuda_fp16.h>
#include <mma.h>
#include <math.h>

using namespace nvcuda;

#define N_NODES 50000
#define M_PAD   50048              // 391 * 128
#define N_EDGES 800000
#define E_TOT   (N_EDGES + N_NODES)
#define IN_DIM  128
#define HID     64
#define HEADS   4
#define OUT_DIM 20
#define NUM_GRAPHS 64
#define NEG_SLOPE 0.2f

// ---------------- scratch (static device globals; no allocation) -------------
__device__ __half g_xh  [M_PAD * IN_DIM];          // x in fp16 (pad rows = 0)
__device__ __half g_w1h [HEADS * HID * IN_DIM];    // W1 fp16
__device__ __half g_w2h [HID * HEADS * HID];       // W2 fp16
__device__ __half g_h1h [M_PAD * HEADS * HID];     // x @ W1^T (fp16)
__device__ __half g_h1oh[M_PAD * HEADS * HID];     // elu(conv1) fp16 (pad rows stay 0)
__device__ __half g_h2h [M_PAD * HID];             // h1o @ W2^T (fp16)
__device__ float  g_as1 [N_NODES * HEADS];
__device__ float  g_ad1 [N_NODES * HEADS];
__device__ float  g_as2 [N_NODES];
__device__ float  g_ad2 [N_NODES];
__device__ int    g_deg   [N_NODES];               // zeroed at module load; re-zeroed by k_scan
__device__ int    g_rowptr[N_NODES + 1];
__device__ int    g_woff  [N_NODES];
__device__ int    g_colsrc[E_TOT];
__device__ float  g_pooled[NUM_GRAPHS * HID];

// ---------------- fused fp32 -> fp16 convert (x pad-zeroed, W1, W2) ----------
#define CV_N1 (M_PAD * IN_DIM)
#define CV_N2 (HEADS * HID * IN_DIM)
#define CV_N3 (HID * HEADS * HID)
__global__ void k_tohalf_all(const float* __restrict__ x,
                             const float* __restrict__ W1,
                             const float* __restrict__ W2) {
    int i = (blockIdx.x * blockDim.x + threadIdx.x) * 4;
    const float* src; __half* dst; int n_valid;
    if (i < CV_N1) { src = x; dst = g_xh; n_valid = N_NODES * IN_DIM; }
    else if (i < CV_N1 + CV_N2) { i -= CV_N1; src = W1; dst = g_w1h; n_valid = CV_N2; }
    else if (i < CV_N1 + CV_N2 + CV_N3) { i -= CV_N1 + CV_N2; src = W2; dst = g_w2h; n_valid = CV_N3; }
    else return;
    float4 v;
    if (i + 3 < n_valid) {
        v = *(const float4*)(src + i);
    } else {
        v.x = (i     < n_valid) ? src[i]     : 0.f;
        v.y = (i + 1 < n_valid) ? src[i + 1] : 0.f;
        v.z = (i + 2 < n_valid) ? src[i + 2] : 0.f;
        v.w = (i + 3 < n_valid) ? src[i + 3] : 0.f;
    }
    __half2 h0 = __floats2half2_rn(v.x, v.y);
    __half2 h1 = __floats2half2_rn(v.z, v.w);
    uint2 p;
    p.x = *(unsigned int*)&h0;
    p.y = *(unsigned int*)&h1;
    *(uint2*)(dst + i) = p;
}

// ---------------- HGEMM (NT) via wmma: Ch[M,N] = half(A[M,K] @ B[N,K]^T) -----
// Block tile 128x64, 8 warps (4x2), warp tile 32x32, BK=64. M%128==0, N%64==0.
__global__ void k_gemm_h(const __half* __restrict__ A, const __half* __restrict__ B,
                         __half* __restrict__ C, int M, int N, int K) {
    __shared__ __half As[128][72];
    __shared__ __half Bs[64][72];
    int tid = threadIdx.x;
    int wid = tid >> 5;
    int wr = wid >> 1;
    int wc = wid & 1;
    int row0 = blockIdx.y * 128;
    int col0 = blockIdx.x * 64;

    wmma::fragment<wmma::accumulator, 16, 16, 16, float> c[2][2];
#pragma unroll
    for (int i = 0; i < 2; i++)
#pragma unroll
        for (int j = 0; j < 2; j++) wmma::fill_fragment(c[i][j], 0.f);

    for (int k0 = 0; k0 < K; k0 += 64) {
#pragma unroll
        for (int l = 0; l < 4; l++) {
            int chunk = tid + l * 256;
            int r = chunk >> 3;
            int c8 = (chunk & 7) * 8;
            *(uint4*)&As[r][c8] = *(const uint4*)(A + (size_t)(row0 + r) * K + k0 + c8);
        }
#pragma unroll
        for (int l = 0; l < 2; l++) {
            int chunk = tid + l * 256;
            int r = chunk >> 3;
            int c8 = (chunk & 7) * 8;
            *(uint4*)&Bs[r][c8] = *(const uint4*)(B + (size_t)(col0 + r) * K + k0 + c8);
        }
        __syncthreads();
#pragma unroll
        for (int kk = 0; kk < 64; kk += 16) {
            wmma::fragment<wmma::matrix_a, 16, 16, 16, __half, wmma::row_major> a0, a1;
            wmma::fragment<wmma::matrix_b, 16, 16, 16, __half, wmma::col_major> b0, b1;
            wmma::load_matrix_sync(a0, &As[wr * 32][kk], 72);
            wmma::load_matrix_sync(a1, &As[wr * 32 + 16][kk], 72);
            wmma::load_matrix_sync(b0, &Bs[wc * 32][kk], 72);
            wmma::load_matrix_sync(b1, &Bs[wc * 32 + 16][kk], 72);
            wmma::mma_sync(c[0][0], a0, b0, c[0][0]);
            wmma::mma_sync(c[0][1], a0, b1, c[0][1]);
            wmma::mma_sync(c[1][0], a1, b0, c[1][0]);
            wmma::mma_sync(c[1][1], a1, b1, c[1][1]);
        }
        __syncthreads();
    }
#pragma unroll
    for (int i = 0; i < 2; i++)
#pragma unroll
        for (int j = 0; j < 2; j++) {
            wmma::fragment<wmma::accumulator, 16, 16, 16, __half> hc;
#pragma unroll
            for (int e = 0; e < hc.num_elements; e++)
                hc.x[e] = __float2half(c[i][j].x[e]);
            wmma::store_matrix_sync(
                C + (size_t)(row0 + wr * 32 + i * 16) * N + col0 + wc * 32 + j * 16,
                hc, N, wmma::mem_row_major);
        }
}

// ---------------- alpha dots from fp16 h (one warp per node-head) ------------
template <int H>
__global__ void k_alpha(const __half* __restrict__ hlin,
                        const float* __restrict__ a_s, const float* __restrict__ a_d,
                        float* __restrict__ as_o, float* __restrict__ ad_o) {
    int gw = (blockIdx.x * blockDim.x + threadIdx.x) >> 5;
    int lane = threadIdx.x & 31;
    if (gw >= N_NODES * H) return;
    int n = gw / H, h = gw % H;
    __half2 hraw = ((const __half2*)(hlin + (size_t)n * H * HID + h * HID))[lane];
    float2 hv = __half22float2(hraw);
    float2 sv = ((const float2*)(a_s + h * HID))[lane];
    float2 dv = ((const float2*)(a_d + h * HID))[lane];
    float s = hv.x * sv.x + hv.y * sv.y;
    float d = hv.x * dv.x + hv.y * dv.y;
#pragma unroll
    for (int o = 16; o > 0; o >>= 1) {
        s += __shfl_xor_sync(0xffffffffu, s, o);
        d += __shfl_xor_sync(0xffffffffu, d, o);
    }
    if (lane == 0) { as_o[gw] = s; ad_o[gw] = d; }
}

// ---------------- CSR build --------------------------------------------------
__global__ void k_deg(const int* __restrict__ ei) {
    int i = blockIdx.x * blockDim.x + threadIdx.x;
    if (i >= E_TOT) return;
    int dst = (i < N_EDGES) ? ei[N_EDGES + i] : (i - N_EDGES);
    atomicAdd(&g_deg[dst], 1);
}

// single block scan; also re-inits g_pooled to -inf and self-zeroes g_deg
// (so the next graph replay's k_deg starts from zero -> deterministic).
__global__ void k_scan() {
    __shared__ int s_w[32];
    int tid = threadIdx.x, lane = tid & 31, w = tid >> 5;
    for (int i = tid; i < NUM_GRAPHS * HID; i += 1024)
        ((int*)g_pooled)[i] = 0xFF800000;   // -inf
    int carry = 0;
    for (int base = 0; base < N_NODES; base += 4096) {
        int i = base + tid * 4;
        int a0 = 0, a1 = 0, a2 = 0, a3 = 0;
        if (i + 3 < N_NODES) {
            int4 v = *(const int4*)&g_deg[i];
            a0 = v.x; a1 = v.y; a2 = v.z; a3 = v.w;
            *(int4*)&g_deg[i] = make_int4(0, 0, 0, 0);
        } else {
            if (i     < N_NODES) { a0 = g_deg[i];     g_deg[i]     = 0; }
            if (i + 1 < N_NODES) { a1 = g_deg[i + 1]; g_deg[i + 1] = 0; }
            if (i + 2 < N_NODES) { a2 = g_deg[i + 2]; g_deg[i + 2] = 0; }
            if (i + 3 < N_NODES) { a3 = g_deg[i + 3]; g_deg[i + 3] = 0; }
        }
        int t = a0 + a1 + a2 + a3;
        int x = t;
#pragma unroll
        for (int o = 1; o < 32; o <<= 1) {
            int u = __shfl_up_sync(0xffffffffu, x, o);
            if (lane >= o) x += u;
        }
        if (lane == 31) s_w[w] = x;
        __syncthreads();
        if (w == 0) {
            int y = s_w[lane];
#pragma unroll
            for (int o = 1; o < 32; o <<= 1) {
                int u = __shfl_up_sync(0xffffffffu, y, o);
                if (lane >= o) y += u;
            }
            s_w[lane] = y;
        }
        __syncthreads();
        int excl = carry + (w ? s_w[w - 1] : 0) + (x - t);
        int r0 = excl, r1 = excl + a0, r2 = r1 + a1, r3 = r2 + a2;
        if (i + 3 < N_NODES) {
            *(int4*)&g_rowptr[i] = make_int4(r0, r1, r2, r3);
            *(int4*)&g_woff[i]   = make_int4(r0, r1, r2, r3);
        } else {
            if (i     < N_NODES) { g_rowptr[i]     = r0; g_woff[i]     = r0; }
            if (i + 1 < N_NODES) { g_rowptr[i + 1] = r1; g_woff[i + 1] = r1; }
            if (i + 2 < N_NODES) { g_rowptr[i + 2] = r2; g_woff[i + 2] = r2; }
            if (i + 3 < N_NODES) { g_rowptr[i + 3] = r3; g_woff[i + 3] = r3; }
        }
        carry += s_w[31];
        __syncthreads();
    }
    if (tid == 0) g_rowptr[N_NODES] = carry;
}

__global__ void k_scatter(const int* __restrict__ ei) {
    int i = blockIdx.x * blockDim.x + threadIdx.x;
    if (i >= E_TOT) return;
    int src, dst;
    if (i < N_EDGES) { src = ei[i]; dst = ei[N_EDGES + i]; }
    else             { src = dst = i - N_EDGES; }
    int pos = atomicAdd(&g_woff[dst], 1);
    g_colsrc[pos] = src;
}

// ---------------- GATConv gather: one warp per NODE, all H heads -------------
// Per 32-edge tile: each lane computes all H exp-weights for one edge (alpha
// loaded as one float4/float), then inner loop broadcasts (src, w[0..H)) and
// does H independent coalesced 128B gathers -> high MLP, no redundant colsrc.
template <int H, bool POOL>
__global__ void k_conv(const __half* __restrict__ hin,
                       const float* __restrict__ as_, const float* __restrict__ ad_,
                       const float* __restrict__ bias, __half* __restrict__ hout,
                       const int* __restrict__ batch, float* __restrict__ pooled) {
    int n = (blockIdx.x * blockDim.x + threadIdx.x) >> 5;
    int lane = threadIdx.x & 31;
    if (n >= N_NODES) return;
    int start = g_rowptr[n], end = g_rowptr[n + 1];

    float adn[H];
#pragma unroll
    for (int h = 0; h < H; h++) adn[h] = ad_[n * H + h];

    float wsum[H], acc0[H], acc1[H];
#pragma unroll
    for (int h = 0; h < H; h++) { wsum[h] = 0.f; acc0[h] = 0.f; acc1[h] = 0.f; }

    const __half2* hb = (const __half2*)hin + lane;

    for (int tile = start; tile < end; tile += 32) {
        int e = tile + lane;
        int s = 0;
        float w[H];
#pragma unroll
        for (int h = 0; h < H; h++) w[h] = 0.f;
        if (e < end) {
            s = g_colsrc[e];
            if (H == 4) {
                float4 av = *(const float4*)(as_ + s * 4);
                float a[4] = {av.x, av.y, av.z, av.w};
#pragma unroll
                for (int h = 0; h < 4; h++) {
                    float t = a[h] + adn[h];
                    t = (t >= 0.f) ? t : NEG_SLOPE * t;
                    w[h] = __expf(t);
                }
            } else {
                float t = as_[s] + adn[0];
                t = (t >= 0.f) ? t : NEG_SLOPE * t;
                w[0] = __expf(t);
            }
        }
#pragma unroll
        for (int h = 0; h < H; h++) wsum[h] += w[h];
        int cnt = min(32, end - tile);
        for (int j = 0; j < cnt; j++) {
            int src = __shfl_sync(0xffffffffu, s, j);
            const __half2* row = hb + (size_t)src * (H * HID / 2);
#pragma unroll
            for (int h = 0; h < H; h++) {
                float wj = __shfl_sync(0xffffffffu, w[h], j);
                float2 v = __half22float2(row[h * (HID / 2)]);
                acc0[h] += v.x * wj;
                acc1[h] += v.y * wj;
            }
        }
    }
#pragma unroll
    for (int h = 0; h < H; h++) {
#pragma unroll
        for (int o = 16; o > 0; o >>= 1)
            wsum[h] += __shfl_xor_sync(0xffffffffu, wsum[h], o);
        float inv = 1.f / (wsum[h] + 1e-16f);
        float o0 = acc0[h] * inv + bias[h * HID + 2 * lane];
        float o1 = acc1[h] * inv + bias[h * HID + 2 * lane + 1];
        o0 = (o0 > 0.f) ? o0 : expm1f(o0);   // elu
        o1 = (o1 > 0.f) ? o1 : expm1f(o1);
        if (POOL) {
            int g = batch[n];
            float* p0 = &pooled[g * HID + 2 * lane];
            float* p1 = p0 + 1;
            if (o0 >= 0.f) atomicMax((int*)p0, __float_as_int(o0));
            else           atomicMin((unsigned int*)p0, __float_as_uint(o0));
            if (o1 >= 0.f) atomicMax((int*)p1, __float_as_int(o1));
            else           atomicMin((unsigned int*)p1, __float_as_uint(o1));
        } else {
            ((__half2*)(hout + (size_t)n * (H * HID) + h * HID))[lane] =
                __floats2half2_rn(o0, o1);
        }
    }
}

// ---------------- final FC ---------------------------------------------------
__global__ void k_fc(const float* __restrict__ fcW, const float* __restrict__ fcb,
                     float* __restrict__ out) {
    int i = blockIdx.x * blockDim.x + threadIdx.x;
    if (i >= NUM_GRAPHS * OUT_DIM) return;
    int g = i / OUT_DIM, o = i % OUT_DIM;
    float acc = fcb[o];
#pragma unroll
    for (int c = 0; c < HID; c++)
        acc += g_pooled[g * HID + c] * fcW[o * HID + c];
    out[i] = acc;
}

// ---------------- stream/event infra (host objects, created once) ------------
struct SideStream {
    cudaStream_t s;
    cudaEvent_t ev_fork, ev_join;
    SideStream() {
        cudaStreamCreateWithFlags(&s, cudaStreamNonBlocking);
        cudaEventCreateWithFlags(&ev_fork, cudaEventDisableTiming);
        cudaEventCreateWithFlags(&ev_join, cudaEventDisableTiming);
    }
};

// ---------------- launch -----------------------------------------------------
extern "C" void kernel_launch(void* const* d_in, const int* in_sizes, int n_in,
                              void* d_out, int out_size) {
    const float* x      = (const float*)d_in[0];
    const int*   ei     = (const int*)  d_in[1];
    const int*   batch  = (const int*)  d_in[2];
    const float* W1     = (const float*)d_in[3];
    const float* a_src1 = (const float*)d_in[4];
    const float* a_dst1 = (const float*)d_in[5];
    const float* b1     = (const float*)d_in[6];
    const float* W2     = (const float*)d_in[7];
    const float* a_src2 = (const float*)d_in[8];
    const float* a_dst2 = (const float*)d_in[9];
    const float* b2     = (const float*)d_in[10];
    const float* fcW    = (const float*)d_in[11];
    const float* fcb    = (const float*)d_in[12];
    float* out = (float*)d_out;

    __half *xh, *w1h, *w2h, *h1h, *h1oh, *h2h;
    float *as1, *ad1, *as2, *ad2, *pooled;
    cudaGetSymbolAddress((void**)&xh,   g_xh);
    cudaGetSymbolAddress((void**)&w1h,  g_w1h);
    cudaGetSymbolAddress((void**)&w2h,  g_w2h);
    cudaGetSymbolAddress((void**)&h1h,  g_h1h);
    cudaGetSymbolAddress((void**)&h1oh, g_h1oh);
    cudaGetSymbolAddress((void**)&h2h,  g_h2h);
    cudaGetSymbolAddress((void**)&as1,  g_as1);
    cudaGetSymbolAddress((void**)&ad1,  g_ad1);
    cudaGetSymbolAddress((void**)&as2,  g_as2);
    cudaGetSymbolAddress((void**)&ad2,  g_ad2);
    cudaGetSymbolAddress((void**)&pooled, g_pooled);

    static SideStream side;   // host-side objects only; created at first call
    const int B = 256;

    // fork: CSR chain on side stream (depends only on edge_index)
    cudaEventRecord(side.ev_fork, 0);
    cudaStreamWaitEvent(side.s, side.ev_fork, 0);
    k_deg<<<(E_TOT + B - 1) / B, B, 0, side.s>>>(ei);
    k_scan<<<1, 1024, 0, side.s>>>();
    k_scatter<<<(E_TOT + B - 1) / B, B, 0, side.s>>>(ei);
    cudaEventRecord(side.ev_join, side.s);

    // main stream: convert -> GEMM1 -> alpha1
    {
        int total = CV_N1 + CV_N2 + CV_N3;
        k_tohalf_all<<<(total / 4 + B - 1) / B, B>>>(x, W1, W2);
    }
    {
        dim3 grid((HEADS * HID) / 64, M_PAD / 128);
        k_gemm_h<<<grid, 256>>>(xh, w1h, h1h, M_PAD, HEADS * HID, IN_DIM);
    }
    k_alpha<HEADS><<<(N_NODES * HEADS * 32 + B - 1) / B, B>>>(h1h, a_src1, a_dst1, as1, ad1);

    // join: conv1 needs CSR + alpha1
    cudaStreamWaitEvent(0, side.ev_join, 0);
    k_conv<HEADS, false><<<(N_NODES * 32 + B - 1) / B, B>>>(
        h1h, as1, ad1, b1, h1oh, nullptr, nullptr);

    // layer 2
    {
        dim3 grid(HID / 64, M_PAD / 128);
        k_gemm_h<<<grid, 256>>>(h1oh, w2h, h2h, M_PAD, HID, HEADS * HID);
    }
    k_alpha<1><<<(N_NODES * 32 + B - 1) / B, B>>>(h2h, a_src2, a_dst2, as2, ad2);
    k_conv<1, true><<<(N_NODES * 32 + B - 1) / B, B>>>(
        h2h, as2, ad2, b2, nullptr, batch, pooled);

    // fc
    k_fc<<<(NUM_GRAPHS * OUT_DIM + B - 1) / B, B>>>(fcW, fcb, out);
}